// round 17
// baseline (speedup 1.0000x reference)
#include <cuda_runtime.h>
#include <stdint.h>

// KVCache update: out = concat(k_cache, v_cache) with rows at pos_ids replaced
// by new k/v. pos_ids int32[16] (int64-layout auto-detected).
// Output f32[2,8,8192,128] = 64 MiB. Traffic floor: 64MB read + 64MB write.
//
// R17 probe: 1024-thread CTAs, 1 CTA/SM (GRID=148, one wave). Same warps/SM
// and in-flight loads as the R16 best (18.27us), but the 8KB s->row table is
// built ONCE per SM and each CTA covers an 8192-float4-contiguous region.
// Everything else = proven config: evict_last loads + __stcs stores,
// persistent grid, MLP=8, chunk-uniform tensor/head.

constexpr int N_HEADS   = 8;
constexpr int CTX       = 8192;
constexpr int HEAD_DIM  = 128;
constexpr int N_NEW     = 16;
constexpr int D4        = HEAD_DIM / 4;              // 32 float4 per row
constexpr int PER_TENSOR_V4 = N_HEADS * CTX * D4;    // 2,097,152
constexpr int TOTAL_V4      = 2 * PER_TENSOR_V4;     // 4,194,304
constexpr int THREADS    = 1024;
constexpr int PER_THREAD = 8;
constexpr int CHUNK_V4   = THREADS * PER_THREAD;     // 8192 float4 = 256 rows, 1 head
constexpr int N_CHUNKS   = TOTAL_V4 / CHUNK_V4;      // 512 (256 K + 256 V)
constexpr int CHUNKS_PER_TENSOR = PER_TENSOR_V4 / CHUNK_V4;  // 256
constexpr int CHUNKS_PER_HEAD   = CTX * D4 / CHUNK_V4;       // 32
constexpr int CTAS_PER_SM = 1;
constexpr int GRID       = 148 * CTAS_PER_SM;        // 148: one wave

__device__ __forceinline__ float4 ld_persist(const float4* p, uint64_t pol) {
    float4 v;
    asm volatile("ld.global.L2::cache_hint.v4.f32 {%0,%1,%2,%3}, [%4], %5;"
                 : "=f"(v.x), "=f"(v.y), "=f"(v.z), "=f"(v.w)
                 : "l"(p), "l"(pol));
    return v;
}

__global__ void __launch_bounds__(THREADS, CTAS_PER_SM)
kvcache_update_kernel(const int* __restrict__ pos32,
                      const float4* __restrict__ knew,
                      const float4* __restrict__ vnew,
                      const float4* __restrict__ kcache,
                      const float4* __restrict__ vcache,
                      float4* __restrict__ out)
{
    __shared__ uint8_t tbl[CTX];   // s -> j+1, 0 = not updated

    // Zero the table: 8192 B = 512 uint4; first 512 threads, 1 each.
    if (threadIdx.x < 512)
        reinterpret_cast<uint4*>(tbl)[threadIdx.x] = make_uint4(0, 0, 0, 0);
    __syncthreads();

    if (threadIdx.x == 0) {
        // int64-vs-int32 layout detection (values < 2^31 -> odd words all zero).
        bool is64 = true;
        #pragma unroll
        for (int i = 1; i < 16; i += 2)
            if (pos32[i] != 0) is64 = false;
        // Sequential fill: last duplicate wins (scatter semantics).
        #pragma unroll
        for (int i = 0; i < N_NEW; i++) {
            int s = is64 ? pos32[2 * i] : pos32[i];
            tbl[s] = (uint8_t)(i + 1);
        }
    }
    __syncthreads();

    // evict_last policy for the cache read stream.
    uint64_t pol;
    asm("createpolicy.fractional.L2::evict_last.b64 %0, 1.0;" : "=l"(pol));

    for (int chunk = blockIdx.x; chunk < N_CHUNKS; chunk += GRID) {
        // Chunk-uniform tensor and head.
        const bool isV = chunk >= CHUNKS_PER_TENSOR;
        const int  tc  = isV ? chunk - CHUNKS_PER_TENSOR : chunk;  // within tensor
        const int  h   = tc / CHUNKS_PER_HEAD;
        const float4* __restrict__ cache = isV ? vcache : kcache;
        const float4* __restrict__ newkv = (isV ? vnew : knew) + h * N_NEW * D4;

        const int rbase = tc * CHUNK_V4 + threadIdx.x;   // index within tensor
        const int obase = chunk * CHUNK_V4 + threadIdx.x;

        float4 vals[PER_THREAD];
        #pragma unroll
        for (int c = 0; c < PER_THREAD; c++) {
            int r  = rbase + c * THREADS;
            int d4 = r & (D4 - 1);
            int s  = (r >> 5) & (CTX - 1);
            int j  = tbl[s];                              // broadcast LDS (row-uniform)
            const float4* src = j ? &newkv[(j - 1) * D4 + d4] : &cache[r];
            vals[c] = ld_persist(src, pol);
        }
        #pragma unroll
        for (int c = 0; c < PER_THREAD; c++)
            __stcs(&out[obase + c * THREADS], vals[c]);   // evict-first stream
    }
}

extern "C" void kernel_launch(void* const* d_in, const int* in_sizes, int n_in,
                              void* d_out, int out_size)
{
    const int*    pos    = (const int*)d_in[0];
    const float4* knew   = (const float4*)d_in[1];
    const float4* vnew   = (const float4*)d_in[2];
    const float4* kcache = (const float4*)d_in[3];
    const float4* vcache = (const float4*)d_in[4];
    float4*       out    = (float4*)d_out;

    kvcache_update_kernel<<<GRID, THREADS>>>(pos, knew, vnew, kcache, vcache, out);
}